// round 1
// baseline (speedup 1.0000x reference)
#include <cuda_runtime.h>
#include <cfloat>
#include <math.h>

#define N_ROWS 65536
#define KDIM   512
#define NE     1024

// ---------------- scratch (no allocations allowed) ----------------
__device__ int   g_idx[N_ROWS];
__device__ int   g_counts[NE];
__device__ float g_bnorm[NE];
__device__ float g_partials[2048];

// ---------------- kernel 1: codebook norms + zero counts ----------------
__global__ void bnorm_kernel(const float* __restrict__ cb) {
    int b = blockIdx.x, t = threadIdx.x;           // 1024 blocks x 128 threads
    const float4 v = *(const float4*)(cb + b * KDIM + t * 4);
    float s = v.x * v.x + v.y * v.y + v.z * v.z + v.w * v.w;
#pragma unroll
    for (int o = 16; o; o >>= 1) s += __shfl_xor_sync(0xffffffffu, s, o);
    __shared__ float w[4];
    if ((t & 31) == 0) w[t >> 5] = s;
    __syncthreads();
    if (t == 0) {
        g_bnorm[b]  = (w[0] + w[1]) + (w[2] + w[3]);
        g_counts[b] = 0;
    }
}

// ---------------- kernel 2: fused GEMM + argmin ----------------
#define ZS_STRIDE 68    // [512][68] transposed z tile (pad to dodge worst conflicts)
#define BS_STRIDE 132   // [16][132] codebook k-chunk

extern __shared__ float smem_f[];

__global__ void __launch_bounds__(256, 1)
fused_kernel(const float* __restrict__ z, const float* __restrict__ cb) {
    float* zs    = smem_f;                      // 512*68  = 34816 floats
    float* bs    = smem_f + 512 * ZS_STRIDE;    // 16*132  = 2112 floats
    float* anorm = bs + 16 * BS_STRIDE;         // 64 floats

    const int tid  = threadIdx.x;
    const int tx   = tid & 15;      // code-column group
    const int ty   = tid >> 4;      // row group
    const int row0 = blockIdx.x * 64;

    // load 64x512 z tile, transposed into zs[k][r]
    for (int i = tid; i < 64 * 128; i += 256) {
        int r = i >> 7, kf4 = i & 127;
        float4 v = *(const float4*)(z + (row0 + r) * KDIM + kf4 * 4);
        int k = kf4 * 4;
        zs[(k + 0) * ZS_STRIDE + r] = v.x;
        zs[(k + 1) * ZS_STRIDE + r] = v.y;
        zs[(k + 2) * ZS_STRIDE + r] = v.z;
        zs[(k + 3) * ZS_STRIDE + r] = v.w;
    }
    __syncthreads();

    // row norms a_r (uniform-shift-safe: exact reduction order is not critical)
    {
        int r = tid >> 2, p = tid & 3;
        float s = 0.f;
        int k0 = p * 128;
        for (int k = k0; k < k0 + 128; ++k) {
            float a = zs[k * ZS_STRIDE + r];
            s = fmaf(a, a, s);
        }
        s += __shfl_xor_sync(0xffffffffu, s, 1);
        s += __shfl_xor_sync(0xffffffffu, s, 2);
        if (p == 0) anorm[r] = s;
    }
    __syncthreads();

    float bestd[4] = {FLT_MAX, FLT_MAX, FLT_MAX, FLT_MAX};
    int   besti[4] = {0, 0, 0, 0};

    for (int jc = 0; jc < 8; ++jc) {            // 8 chunks of 128 codes
        const int j0 = jc * 128;
        float acc[4][8];
#pragma unroll
        for (int ii = 0; ii < 4; ++ii)
#pragma unroll
            for (int jj = 0; jj < 8; ++jj) acc[ii][jj] = 0.f;

        for (int kc = 0; kc < 32; ++kc) {       // K in chunks of 16
            const int k0 = kc * 16;
            __syncthreads();
            // load 16x128 codebook chunk, transposed into bs[k][j]
#pragma unroll
            for (int l = 0; l < 2; ++l) {
                int idx = tid * 2 + l;          // 0..511
                int j   = idx >> 2;             // 0..127
                int kq  = (idx & 3) << 2;       // 0,4,8,12
                float4 v = *(const float4*)(cb + (j0 + j) * KDIM + k0 + kq);
                bs[(kq + 0) * BS_STRIDE + j] = v.x;
                bs[(kq + 1) * BS_STRIDE + j] = v.y;
                bs[(kq + 2) * BS_STRIDE + j] = v.z;
                bs[(kq + 3) * BS_STRIDE + j] = v.w;
            }
            __syncthreads();
#pragma unroll
            for (int k = 0; k < 16; ++k) {
                float4 av = *(const float4*)(zs + (k0 + k) * ZS_STRIDE + ty * 4);
                float4 b0 = *(const float4*)(bs + k * BS_STRIDE + tx * 8);
                float4 b1 = *(const float4*)(bs + k * BS_STRIDE + tx * 8 + 4);
                float a[4] = {av.x, av.y, av.z, av.w};
                float b[8] = {b0.x, b0.y, b0.z, b0.w, b1.x, b1.y, b1.z, b1.w};
#pragma unroll
                for (int ii = 0; ii < 4; ++ii)
#pragma unroll
                    for (int jj = 0; jj < 8; ++jj)
                        acc[ii][jj] = fmaf(a[ii], b[jj], acc[ii][jj]);
            }
        }

        // d = fl(fl(a + b) - 2c), exactly mirroring the reference expression
#pragma unroll
        for (int ii = 0; ii < 4; ++ii) {
            float an = anorm[ty * 4 + ii];
#pragma unroll
            for (int jj = 0; jj < 8; ++jj) {
                int col = j0 + tx * 8 + jj;
                float s = __fadd_rn(an, g_bnorm[col]);
                float d = __fadd_rn(s, -2.0f * acc[ii][jj]);
                if (d < bestd[ii]) { bestd[ii] = d; besti[ii] = col; }  // strict <: first-index on ties
            }
        }
    }

    // reduce across the 16 tx lanes (same half-warp: ty is constant for xor<16)
#pragma unroll
    for (int off = 8; off; off >>= 1) {
#pragma unroll
        for (int ii = 0; ii < 4; ++ii) {
            float od = __shfl_xor_sync(0xffffffffu, bestd[ii], off);
            int   oi = __shfl_xor_sync(0xffffffffu, besti[ii], off);
            if (od < bestd[ii] || (od == bestd[ii] && oi < besti[ii])) {
                bestd[ii] = od; besti[ii] = oi;
            }
        }
    }
    if (tx == 0) {
#pragma unroll
        for (int ii = 0; ii < 4; ++ii) {
            int r = row0 + ty * 4 + ii;
            g_idx[r] = besti[ii];
            atomicAdd(&g_counts[besti[ii]], 1);   // integer: deterministic
        }
    }
}

// ---------------- kernel 3: gather, z_q_st, idx-as-float, loss partials ----------------
__global__ void out_kernel(const float* __restrict__ z, const float* __restrict__ cb,
                           float* __restrict__ out, int idx_base) {
    const int tid = threadIdx.x;
    const int g0  = blockIdx.x * 256 + tid;   // float4 index start; grid 2048x256, 16 iters
    float s = 0.f;
#pragma unroll 4
    for (int it = 0; it < 16; ++it) {
        int g   = g0 + it * 524288;           // 2048*256
        int row = g >> 7;                     // 128 float4 per row
        int kk  = (g & 127) << 2;
        int id  = g_idx[row];
        float4 zv = *(const float4*)(z  + row * KDIM + kk);
        float4 qv = *(const float4*)(cb + id  * KDIM + kk);
        float t0 = __fsub_rn(qv.x, zv.x);
        float t1 = __fsub_rn(qv.y, zv.y);
        float t2 = __fsub_rn(qv.z, zv.z);
        float t3 = __fsub_rn(qv.w, zv.w);
        float* dst = out + 1 + (g << 2);      // out+1 is misaligned for float4 -> scalar stores
        dst[0] = __fadd_rn(zv.x, t0);
        dst[1] = __fadd_rn(zv.y, t1);
        dst[2] = __fadd_rn(zv.z, t2);
        dst[3] = __fadd_rn(zv.w, t3);
        s += t0 * t0 + t1 * t1 + t2 * t2 + t3 * t3;
    }
    if (g0 < N_ROWS) out[idx_base + g0] = (float)g_idx[g0];

    __shared__ float red[256];
    red[tid] = s;
    __syncthreads();
#pragma unroll
    for (int o = 128; o; o >>= 1) {
        if (tid < o) red[tid] += red[tid + o];
        __syncthreads();
    }
    if (tid == 0) g_partials[blockIdx.x] = red[0];
}

// ---------------- kernel 4: finalize loss + perplexity ----------------
__global__ void fin_kernel(float* __restrict__ out, int out_size) {
    __shared__ float red[1024];
    const int t = threadIdx.x;

    red[t] = g_partials[t] + g_partials[t + 1024];
    __syncthreads();
#pragma unroll
    for (int o = 512; o; o >>= 1) {
        if (t < o) red[t] += red[t + o];
        __syncthreads();
    }
    float total = red[0];
    __syncthreads();

    float e = (float)g_counts[t] * (1.0f / 65536.0f);
    red[t] = e * logf(e + 1e-10f);
    __syncthreads();
#pragma unroll
    for (int o = 512; o; o >>= 1) {
        if (t < o) red[t] += red[t + o];
        __syncthreads();
    }
    if (t == 0) {
        float m = total / 33554432.0f;                 // mean((z_q - z)^2)
        out[0] = __fadd_rn(m, __fmul_rn(0.25f, m));    // m + BETA*m
        out[out_size - 1] = expf(-red[0]);             // perplexity
    }
}

// ---------------- launch ----------------
extern "C" void kernel_launch(void* const* d_in, const int* in_sizes, int n_in,
                              void* d_out, int out_size) {
    const float* z  = (const float*)d_in[0];   // (16,4096,512) -> 65536 x 512
    const float* cb = (const float*)d_in[1];   // (1024,512)
    float* out = (float*)d_out;

    const int smem_bytes = (512 * ZS_STRIDE + 16 * BS_STRIDE + 64) * (int)sizeof(float);
    cudaFuncSetAttribute(fused_kernel, cudaFuncAttributeMaxDynamicSharedMemorySize, smem_bytes);

    // output layout: [loss(1), z_q_st(33554432), idx(65536), perplexity(1)]
    const int idx_base = out_size - 1 - N_ROWS;

    bnorm_kernel<<<NE, 128>>>(cb);
    fused_kernel<<<N_ROWS / 64, 256, smem_bytes>>>(z, cb);
    out_kernel<<<2048, 256>>>(z, cb, out, idx_base);
    fin_kernel<<<1, 1024>>>(out, out_size);
}

// round 3
// speedup vs baseline: 1.0805x; 1.0805x over previous
#include <cuda_runtime.h>
#include <cuda_bf16.h>
#include <cfloat>
#include <math.h>
#include <stdint.h>

#define N_ROWS 65536
#define KDIM   512
#define NE     1024
#define NG     8          // column groups of 128 codes
#define SLOTS  16
#define MARGIN 1.0e-2f

// ---------------- device scratch (no allocations allowed) ----------------
__device__ __align__(16) __nv_bfloat16 g_zh[N_ROWS * KDIM];
__device__ __align__(16) __nv_bfloat16 g_eh[NE * KDIM];
__device__ float g_bnorm[NE];
__device__ int   g_idx[N_ROWS];
__device__ int   g_counts[NE];
__device__ float g_partials[2048];
__device__ float g_cmin[N_ROWS * NG];
__device__ int   g_ccnt[N_ROWS * NG];
__device__ float g_cd[(size_t)N_ROWS * NG * SLOTS];
__device__ int   g_cj[(size_t)N_ROWS * NG * SLOTS];

// ---------------- helpers ----------------
__device__ __forceinline__ uint32_t smem_u32(const void* p) {
    uint32_t a;
    asm("{ .reg .u64 t; cvta.to.shared.u64 t, %1; cvt.u32.u64 %0, t; }" : "=r"(a) : "l"(p));
    return a;
}
#define SW128(o) ((o) ^ (((o) >> 3) & 0x70))

__device__ __forceinline__ void cp_async16(uint32_t saddr, const void* gptr) {
    asm volatile("cp.async.cg.shared.global [%0], [%1], 16;"
                 :: "r"(saddr), "l"(__cvta_generic_to_global(gptr)) : "memory");
}
__device__ __forceinline__ void cp_commit() {
    asm volatile("cp.async.commit_group;" ::: "memory");
}
__device__ __forceinline__ void ldsm4(uint32_t* r, uint32_t a) {
    asm volatile("ldmatrix.sync.aligned.m8n8.x4.shared.b16 {%0,%1,%2,%3}, [%4];"
                 : "=r"(r[0]), "=r"(r[1]), "=r"(r[2]), "=r"(r[3]) : "r"(a));
}
__device__ __forceinline__ void mma16816(float* c, const uint32_t* a, uint32_t b0, uint32_t b1) {
    asm volatile(
        "mma.sync.aligned.m16n8k16.row.col.f32.bf16.bf16.f32 "
        "{%0,%1,%2,%3}, {%4,%5,%6,%7}, {%8,%9}, {%0,%1,%2,%3};"
        : "+f"(c[0]), "+f"(c[1]), "+f"(c[2]), "+f"(c[3])
        : "r"(a[0]), "r"(a[1]), "r"(a[2]), "r"(a[3]), "r"(b0), "r"(b1));
}

// ---------------- prep kernels ----------------
__global__ void prep_z(const float* __restrict__ z) {
    int t = blockIdx.x * 256 + threadIdx.x;
    float4 v = ((const float4*)z)[t];
    __nv_bfloat162* dst = (__nv_bfloat162*)g_zh;
    dst[2 * t]     = __floats2bfloat162_rn(v.x, v.y);
    dst[2 * t + 1] = __floats2bfloat162_rn(v.z, v.w);
}

__global__ void prep_cb(const float* __restrict__ cb) {
    int b = blockIdx.x, t = threadIdx.x;
    const float4 v = *(const float4*)(cb + b * KDIM + t * 4);
    __nv_bfloat162* dst = (__nv_bfloat162*)(g_eh + b * KDIM);
    dst[2 * t]     = __floats2bfloat162_rn(v.x, v.y);
    dst[2 * t + 1] = __floats2bfloat162_rn(v.z, v.w);
    float s = v.x * v.x + v.y * v.y + v.z * v.z + v.w * v.w;
#pragma unroll
    for (int o = 16; o; o >>= 1) s += __shfl_xor_sync(0xffffffffu, s, o);
    __shared__ float w[4];
    if ((t & 31) == 0) w[t >> 5] = s;
    __syncthreads();
    if (t == 0) {
        g_bnorm[b]  = (w[0] + w[1]) + (w[2] + w[3]);
        g_counts[b] = 0;
    }
}

// ---------------- stage 1: bf16 HMMA GEMM + candidate collection ----------------
// smem: two stage buffers  A[128][64] bf16 (16KB) + B[128][64] bf16 (16KB)  = 64KB
// epilogue reuses smem as  ds[128][130] float                               = 66.5KB
#define SM_A(buf) ((buf) ? 32768 : 0)
#define SM_B(buf) ((buf) ? 49152 : 16384)
#define GEMM_SMEM 66560

extern __shared__ __align__(1024) char smem[];

__global__ void __launch_bounds__(256, 2)
gemm_kernel() {
    const uint32_t sb = smem_u32(smem);
    const int tid = threadIdx.x, wid = tid >> 5, lid = tid & 31;
    const int row0 = (blockIdx.x >> 3) * 128;
    const int cg   = blockIdx.x & 7;
    const int m0w  = (wid & 3) * 32;   // warp rows within tile
    const int n0w  = (wid >> 2) * 64;  // warp cols within tile

    // per-thread load slots: 8 x 16B chunks (4 A + 4 B)
    auto load_tile = [&](int kc, int buf) {
#pragma unroll
        for (int i = 0; i < 4; ++i) {
            int u = tid + i * 256;                 // 0..1023 A chunks
            int r = u >> 3, c = u & 7;
            cp_async16(sb + SM_A(buf) + SW128(r * 128 + c * 16),
                       g_zh + (size_t)(row0 + r) * KDIM + kc * 64 + c * 8);
        }
#pragma unroll
        for (int i = 0; i < 4; ++i) {
            int u = tid + i * 256;
            int r = u >> 3, c = u & 7;
            cp_async16(sb + SM_B(buf) + SW128(r * 128 + c * 16),
                       g_eh + (size_t)(cg * 128 + r) * KDIM + kc * 64 + c * 8);
        }
        cp_commit();
    };

    float acc[2][8][4];
#pragma unroll
    for (int mi = 0; mi < 2; ++mi)
#pragma unroll
        for (int nj = 0; nj < 8; ++nj)
#pragma unroll
            for (int q = 0; q < 4; ++q) acc[mi][nj][q] = 0.f;

    load_tile(0, 0);

    for (int kc = 0; kc < 8; ++kc) {
        const int buf = kc & 1;
        if (kc < 7) {
            load_tile(kc + 1, buf ^ 1);
            asm volatile("cp.async.wait_group 1;" ::: "memory");
        } else {
            asm volatile("cp.async.wait_group 0;" ::: "memory");
        }
        __syncthreads();

        const uint32_t As = sb + SM_A(buf), Bs = sb + SM_B(buf);
#pragma unroll
        for (int ks = 0; ks < 4; ++ks) {
            const int k0 = ks * 16;
            uint32_t a[2][4], b[4][4];
#pragma unroll
            for (int mi = 0; mi < 2; ++mi) {
                int r = m0w + mi * 16 + (lid & 15);
                int kcol = k0 + (lid >> 4) * 8;
                ldsm4(a[mi], As + SW128(r * 128 + kcol * 2));
            }
#pragma unroll
            for (int ni = 0; ni < 4; ++ni) {
                int nr = n0w + ni * 16 + (lid & 7) + ((lid >> 4) << 3);
                int kcol = k0 + ((lid >> 3) & 1) * 8;
                ldsm4(b[ni], Bs + SW128(nr * 128 + kcol * 2));
            }
#pragma unroll
            for (int mi = 0; mi < 2; ++mi)
#pragma unroll
                for (int nj = 0; nj < 8; ++nj)
                    mma16816(acc[mi][nj], a[mi],
                             b[nj >> 1][(nj & 1) * 2], b[nj >> 1][(nj & 1) * 2 + 1]);
        }
        __syncthreads();
    }

    // epilogue: accumulators -> smem ds[128][130]
    float* ds = (float*)smem;
    const int lr = lid >> 2, lc = (lid & 3) * 2;
#pragma unroll
    for (int mi = 0; mi < 2; ++mi)
#pragma unroll
        for (int nj = 0; nj < 8; ++nj) {
            int row = m0w + mi * 16 + lr;
            int col = n0w + nj * 8 + lc;
            ds[row * 130 + col]           = acc[mi][nj][0];
            ds[row * 130 + col + 1]       = acc[mi][nj][1];
            ds[(row + 8) * 130 + col]     = acc[mi][nj][2];
            ds[(row + 8) * 130 + col + 1] = acc[mi][nj][3];
        }
    __syncthreads();

    if (tid < 128) {
        const int row = row0 + tid;
        float bmin = FLT_MAX;
        int cnt = 0;
        const size_t base = ((size_t)row * NG + cg) * SLOTS;
        for (int c = 0; c < 128; ++c) {
            float d = fmaf(-2.0f, ds[tid * 130 + c], g_bnorm[cg * 128 + c]);
            if (d < bmin + MARGIN) {
                if (cnt < SLOTS) { g_cd[base + cnt] = d; g_cj[base + cnt] = cg * 128 + c; }
                cnt++;
                if (d < bmin) bmin = d;
            }
        }
        g_cmin[row * NG + cg] = bmin;
        g_ccnt[row * NG + cg] = cnt;
    }
}

// ---------------- stage 2: exact fp32 rescore of candidates ----------------
__global__ void rescore_kernel(const float* __restrict__ z, const float* __restrict__ cb) {
    const int wid = threadIdx.x >> 5, lid = threadIdx.x & 31;
    const int row = blockIdx.x * 8 + wid;

    const float4* zr = (const float4*)(z + (size_t)row * KDIM) + lid;
    const float4 z0 = zr[0], z1 = zr[32], z2 = zr[64], z3 = zr[96];

    float s = 0.f;
    s = fmaf(z0.x, z0.x, s); s = fmaf(z0.y, z0.y, s); s = fmaf(z0.z, z0.z, s); s = fmaf(z0.w, z0.w, s);
    s = fmaf(z1.x, z1.x, s); s = fmaf(z1.y, z1.y, s); s = fmaf(z1.z, z1.z, s); s = fmaf(z1.w, z1.w, s);
    s = fmaf(z2.x, z2.x, s); s = fmaf(z2.y, z2.y, s); s = fmaf(z2.z, z2.z, s); s = fmaf(z2.w, z2.w, s);
    s = fmaf(z3.x, z3.x, s); s = fmaf(z3.y, z3.y, s); s = fmaf(z3.z, z3.z, s); s = fmaf(z3.w, z3.w, s);
#pragma unroll
    for (int o = 16; o; o >>= 1) s += __shfl_xor_sync(0xffffffffu, s, o);
    const float anorm = s;

    float gmin = FLT_MAX;
    bool ovf = false;
    int cnts[NG];
#pragma unroll
    for (int cg = 0; cg < NG; ++cg) {
        float m = g_cmin[row * NG + cg];
        if (m < gmin) gmin = m;
        int c = g_ccnt[row * NG + cg];
        cnts[cg] = c;
        if (c > SLOTS) ovf = true;
    }

    float bestd = FLT_MAX;
    int bestj = NE;
    auto eval = [&](int j) {
        const float4* cr = (const float4*)(cb + (size_t)j * KDIM) + lid;
        const float4 c0 = cr[0], c1 = cr[32], c2 = cr[64], c3 = cr[96];
        float t = 0.f;
        t = fmaf(z0.x, c0.x, t); t = fmaf(z0.y, c0.y, t); t = fmaf(z0.z, c0.z, t); t = fmaf(z0.w, c0.w, t);
        t = fmaf(z1.x, c1.x, t); t = fmaf(z1.y, c1.y, t); t = fmaf(z1.z, c1.z, t); t = fmaf(z1.w, c1.w, t);
        t = fmaf(z2.x, c2.x, t); t = fmaf(z2.y, c2.y, t); t = fmaf(z2.z, c2.z, t); t = fmaf(z2.w, c2.w, t);
        t = fmaf(z3.x, c3.x, t); t = fmaf(z3.y, c3.y, t); t = fmaf(z3.z, c3.z, t); t = fmaf(z3.w, c3.w, t);
#pragma unroll
        for (int o = 16; o; o >>= 1) t += __shfl_xor_sync(0xffffffffu, t, o);
        float d = __fadd_rn(__fadd_rn(anorm, g_bnorm[j]), -2.0f * t);
        if (d < bestd || (d == bestd && j < bestj)) { bestd = d; bestj = j; }
    };

    if (!ovf) {
        for (int cg = 0; cg < NG; ++cg) {
            const size_t base = ((size_t)row * NG + cg) * SLOTS;
            for (int sI = 0; sI < cnts[cg]; ++sI)
                if (g_cd[base + sI] <= gmin + MARGIN) eval(g_cj[base + sI]);
        }
    } else {
        for (int j = 0; j < NE; ++j) eval(j);
    }

    if (lid == 0) {
        g_idx[row] = bestj;
        atomicAdd(&g_counts[bestj], 1);
    }
}

// ---------------- output pass ----------------
__global__ void out_kernel(const float* __restrict__ z, const float* __restrict__ cb,
                           float* __restrict__ out, int idx_base) {
    const int tid = threadIdx.x;
    const int g0  = blockIdx.x * 256 + tid;
    float s = 0.f;
#pragma unroll 4
    for (int it = 0; it < 16; ++it) {
        int g   = g0 + it * 524288;
        int row = g >> 7;
        int kk  = (g & 127) << 2;
        int id  = g_idx[row];
        float4 zv = *(const float4*)(z  + (size_t)row * KDIM + kk);
        float4 qv = *(const float4*)(cb + (size_t)id  * KDIM + kk);
        float t0 = __fsub_rn(qv.x, zv.x);
        float t1 = __fsub_rn(qv.y, zv.y);
        float t2 = __fsub_rn(qv.z, zv.z);
        float t3 = __fsub_rn(qv.w, zv.w);
        float* dst = out + 1 + ((size_t)g << 2);
        dst[0] = __fadd_rn(zv.x, t0);
        dst[1] = __fadd_rn(zv.y, t1);
        dst[2] = __fadd_rn(zv.z, t2);
        dst[3] = __fadd_rn(zv.w, t3);
        s += t0 * t0 + t1 * t1 + t2 * t2 + t3 * t3;
    }
    if (g0 < N_ROWS) out[idx_base + g0] = (float)g_idx[g0];

    __shared__ float red[256];
    red[tid] = s;
    __syncthreads();
#pragma unroll
    for (int o = 128; o; o >>= 1) {
        if (tid < o) red[tid] += red[tid + o];
        __syncthreads();
    }
    if (tid == 0) g_partials[blockIdx.x] = red[0];
}

// ---------------- finalize ----------------
__global__ void fin_kernel(float* __restrict__ out, int out_size) {
    __shared__ float red[1024];
    const int t = threadIdx.x;
    red[t] = g_partials[t] + g_partials[t + 1024];
    __syncthreads();
#pragma unroll
    for (int o = 512; o; o >>= 1) {
        if (t < o) red[t] += red[t + o];
        __syncthreads();
    }
    float total = red[0];
    __syncthreads();
    float e = (float)g_counts[t] * (1.0f / 65536.0f);
    red[t] = e * logf(e + 1e-10f);
    __syncthreads();
#pragma unroll
    for (int o = 512; o; o >>= 1) {
        if (t < o) red[t] += red[t + o];
        __syncthreads();
    }
    if (t == 0) {
        float m = total / 33554432.0f;
        out[0] = __fadd_rn(m, __fmul_rn(0.25f, m));
        out[out_size - 1] = expf(-red[0]);
    }
}

// ---------------- launch ----------------
extern "C" void kernel_launch(void* const* d_in, const int* in_sizes, int n_in,
                              void* d_out, int out_size) {
    const float* z  = (const float*)d_in[0];
    const float* cb = (const float*)d_in[1];
    float* out = (float*)d_out;
    const int idx_base = out_size - 1 - N_ROWS;

    cudaFuncSetAttribute(gemm_kernel, cudaFuncAttributeMaxDynamicSharedMemorySize, GEMM_SMEM);

    prep_cb<<<NE, 128>>>(cb);
    prep_z<<<32768, 256>>>(z);
    gemm_kernel<<<4096, 256, GEMM_SMEM>>>();
    rescore_kernel<<<8192, 256>>>(z, cb);
    out_kernel<<<2048, 256>>>(z, cb, out, idx_base);
    fin_kernel<<<1, 1024>>>(out, out_size);
}